// round 8
// baseline (speedup 1.0000x reference)
#include <cuda_runtime.h>
#include <math.h>

#define EPSF 1e-8f
#define NBC 64
#define NN 20
#define LPB 16
#define TPB (LPB*32)

// weights region (floats): duplicated-pair layouts (u64 per element)
static constexpr int OW0D = 0;       // 15 x 65 u64 = 1950 fl (pad 1952)
static constexpr int OW1D = 1952;    // 64 x 65 u64 = 8320 fl
static constexpr int OW2D = 10272;   // 64 u64 = 128 fl
static constexpr int OB0D = 10400;   // 128
static constexpr int OB1D = 10528;   // 128
static constexpr int OMISC = 10656;  // 8
static constexpr int WFL = 10664;
// per-lane offsets (floats); mid region shared (lifetime-aliased)
static constexpr int LNDN = 0, LNOR = 60, LNEWR = 240, LP = 240, LFCR = 260, LGO = 260,
    LSO = 280, LZ = 290, LENC = LZ, LGZ = 310, LGPRE = 330, LSC = 350,
    LDRW = 352, LRR = 544, LSEL = 608, LFEAT = 352, LGT = 352, LGF = 352,
    LH1 = 1632, LANE_F = 2912;
static constexpr int SMEM_FLOATS = WFL + LPB * LANE_F;   // 57256 fl = 229024 B

typedef unsigned long long u64;
__device__ __forceinline__ u64 pk2(float a){ u64 r; asm("mov.b64 %0, {%1, %1};":"=l"(r):"f"(a)); return r; }
__device__ __forceinline__ u64 pk(float a,float b){ u64 r; asm("mov.b64 %0, {%1, %2};":"=l"(r):"f"(a),"f"(b)); return r; }
__device__ __forceinline__ void upk(u64 v,float&a,float&b){ asm("mov.b64 {%0, %1}, %2;":"=f"(a),"=f"(b):"l"(v)); }
__device__ __forceinline__ void fma2(u64&c,u64 a,u64 b){ asm("fma.rn.f32x2 %0, %1, %2, %0;":"+l"(c):"l"(a),"l"(b)); }
__device__ __forceinline__ u64 fma2o(u64 a,u64 b,u64 c){ u64 d; asm("fma.rn.f32x2 %0, %1, %2, %3;":"=l"(d):"l"(a),"l"(b),"l"(c)); return d; }
__device__ __forceinline__ u64 mul2(u64 a,u64 b){ u64 d; asm("mul.rn.f32x2 %0, %1, %2;":"=l"(d):"l"(a),"l"(b)); return d; }
__device__ __forceinline__ u64 add2(u64 a,u64 b){ u64 d; asm("add.rn.f32x2 %0, %1, %2;":"=l"(d):"l"(a),"l"(b)); return d; }
__device__ __forceinline__ float ex2a(float x){ float r; asm("ex2.approx.f32 %0, %1;":"=f"(r):"f"(x)); return r; }
__device__ __forceinline__ float lg2a(float x){ float r; asm("lg2.approx.f32 %0, %1;":"=f"(r):"f"(x)); return r; }
__device__ __forceinline__ float rcpa(float x){ float r; asm("rcp.approx.f32 %0, %1;":"=f"(r):"f"(x)); return r; }
__device__ __forceinline__ float tanhfst(float x){
    float e = ex2a(x * 2.885390082f);
    return fmaf(-2.0f, rcpa(e + 1.0f), 1.0f);
}
__device__ __forceinline__ u64 tanh2(u64 v){
    u64 xe = mul2(v, pk2(2.885390082f));
    float a,b; upk(xe,a,b);
    u64 e = pk(ex2a(a), ex2a(b));
    u64 r = add2(e, pk2(1.0f));
    float c,d; upk(r,c,d);
    u64 rc = pk(rcpa(c), rcpa(d));
    return fma2o(rc, pk2(-2.0f), pk2(1.0f));
}

__global__ __launch_bounds__(TPB, 1)
void ep_kernel(const float* __restrict__ dr, const float* __restrict__ orientation,
               const float* __restrict__ n_or,
               const float* __restrict__ W0, const float* __restrict__ b0,
               const float* __restrict__ W1, const float* __restrict__ b1,
               const float* __restrict__ W2, const float* __restrict__ b2,
               const float* __restrict__ f1, const float* __restrict__ f2,
               float* __restrict__ out, int B)
{
    extern __shared__ float sm[];
    const int tid = threadIdx.x;
    {
        float2* w0d = (float2*)(sm + OW0D);
        for (int idx = tid; idx < 960; idx += TPB)  { int i=idx>>6, j=idx&63; float v=W0[idx]; w0d[i*65+j]=make_float2(v,v); }
        float2* w1d = (float2*)(sm + OW1D);
        for (int idx = tid; idx < 4096; idx += TPB) { int k=idx>>6, j=idx&63; float v=W1[idx]; w1d[k*65+j]=make_float2(v,v); }
        if (tid < 64) {
            float v=W2[tid]; ((float2*)(sm+OW2D))[tid]=make_float2(v,v);
            v=b0[tid]; ((float2*)(sm+OB0D))[tid]=make_float2(v,v);
            v=b1[tid]; ((float2*)(sm+OB1D))[tid]=make_float2(v,v);
        }
    }
    if (tid == 0) {
        sm[OMISC] = b2[0];
        #pragma unroll
        for (int j = 0; j < 3; j++) {
            float a=f1[j]; sm[OMISC+1+j]=a*a+EPSF;
            float p=f2[j]; sm[OMISC+4+j]=p*p+EPSF;
        }
    }
    __syncthreads();

    const u64* W0p = (const u64*)(sm + OW0D);
    const u64* W1p = (const u64*)(sm + OW1D);
    const u64* W2p = (const u64*)(sm + OW2D);
    const u64* B0p = (const u64*)(sm + OB0D);
    const u64* B1p = (const u64*)(sm + OB1D);

    const int li = tid >> 5, t = tid & 31;
    const int s = t & 15, half = t >> 4;
    const int batch0 = blockIdx.x * LPB + li;
    const bool wr = batch0 < B;
    const int batch = wr ? batch0 : 0;
    float* L = sm + WFL + li * LANE_F;
    int* selp = (int*)(L + LSEL);

    // A: stage dr + orientation
    {
        const float4* src = (const float4*)(dr + (size_t)batch * 192);
        float4* dst = (float4*)(L + LDRW);
        dst[t] = src[t];
        if (t < 16) dst[t+32] = src[t+32];
        if (t < 9) L[LSO+t] = orientation[(size_t)batch*9 + t];
    }
    __syncwarp();
    // B: radii
    #pragma unroll
    for (int c = 0; c < 2; c++) {
        int u = 2*t+c;
        float x=L[LDRW+u*3]+EPSF, y=L[LDRW+u*3+1]+EPSF, z=L[LDRW+u*3+2]+EPSF;
        L[LRR+u] = sqrtf(x*x+y*y+z*z);
    }
    __syncwarp();
    // C: stable rank
    {
        float Ru[2]; int rk[2];
        #pragma unroll
        for (int c=0;c<2;c++){ Ru[c]=L[LRR+2*t+c]; rk[c]=0; }
        const float4* R4 = (const float4*)(L + LRR);
        #pragma unroll 4
        for (int v4=0; v4<16; v4++){
            float4 rv = R4[v4]; int v = 4*v4;
            #pragma unroll
            for (int c=0;c<2;c++){
                int u = 2*t+c;
                rk[c] += (rv.x<Ru[c])||(rv.x==Ru[c]&&v  <u);
                rk[c] += (rv.y<Ru[c])||(rv.y==Ru[c]&&v+1<u);
                rk[c] += (rv.z<Ru[c])||(rv.z==Ru[c]&&v+2<u);
                rk[c] += (rv.w<Ru[c])||(rv.w==Ru[c]&&v+3<u);
            }
        }
        #pragma unroll
        for (int c=0;c<2;c++) if (rk[c] < NN) selp[rk[c]] = 2*t+c;
    }
    __syncwarp();
    // D: gather top-20
    if (t < NN) {
        int u = selp[t];
        float Rv = L[LRR+u];
        L[LNEWR+t] = Rv;
        float inv = 1.0f / Rv;
        L[LNDN+t*3+0] = (L[LDRW+u*3+0]+EPSF)*inv;
        L[LNDN+t*3+1] = (L[LDRW+u*3+1]+EPSF)*inv;
        L[LNDN+t*3+2] = (L[LDRW+u*3+2]+EPSF)*inv;
        L[LFCR+t] = (Rv > 4.8f) ? 0.0f : (0.5f*cospif(Rv*(1.0f/4.8f)) + 0.5f);
        const float* np_ = n_or + ((size_t)batch*NBC + u)*9;
        #pragma unroll
        for (int e = 0; e < 9; e++) L[LNOR+t*9+e] = np_[e];
    }
    __syncwarp();
    // E: features featT[i][n], stride 20 (over dead LDRW)
    {
        int n = (t * 0x8889) >> 19;
        int i = t - n*15;
        #pragma unroll
        for (int it = 0; it < 10; it++) {
            int p = t + 32*it;
            if (p < 300) {
                const float* nd = L+LNDN+n*3; const float* NO = L+LNOR+n*9; const float* O = L+LSO;
                float v;
                if (i < 3)      v = nd[0]*O[i]   + nd[1]*O[3+i]   + nd[2]*O[6+i];
                else if (i < 6){ int h=i-3; v = nd[0]*NO[h] + nd[1]*NO[3+h] + nd[2]*NO[6+h]; }
                else { int l=(i-6)/3, m=(i-6)%3; v = O[l]*NO[m] + O[3+l]*NO[3+m] + O[6+l]*NO[6+m]; }
                L[LFEAT + i*20 + n] = v;
            }
            n += 2; i += 2;
            if (i >= 15) { i -= 15; n += 1; }
        }
    }
    __syncwarp();

    u64 acc[20];
    // F: GEMM1 -> h1
    #pragma unroll
    for (int i=0;i<4;i++){ u64 bb=B0p[s+16*i];
        #pragma unroll
        for (int q=0;q<5;q++) acc[i*5+q]=bb; }
    #pragma unroll 5
    for (int k=0;k<15;k++){
        u64 wA=W0p[k*65+s],    wB=W0p[k*65+s+16];
        u64 wC=W0p[k*65+s+32], wD=W0p[k*65+s+48];
        const u64* ap=(const u64*)(L+LFEAT+k*20) + 5*half;
        #pragma unroll
        for (int q=0;q<5;q++){ u64 av=ap[q];
            fma2(acc[q],wA,av); fma2(acc[5+q],wB,av);
            fma2(acc[10+q],wC,av); fma2(acc[15+q],wD,av); }
    }
    #pragma unroll
    for (int i=0;i<4;i++){
        u64* hr=(u64*)(L+LH1+(s+16*i)*20) + 5*half;
        #pragma unroll
        for (int q=0;q<5;q++) hr[q]=tanh2(acc[i*5+q]);
    }
    __syncwarp();
    // G: GEMM2 -> h2 (registers only)
    #pragma unroll
    for (int i=0;i<4;i++){ u64 bb=B1p[s+16*i];
        #pragma unroll
        for (int q=0;q<5;q++) acc[i*5+q]=bb; }
    #pragma unroll 8
    for (int k=0;k<64;k++){
        u64 wA=W1p[k*65+s],    wB=W1p[k*65+s+16];
        u64 wC=W1p[k*65+s+32], wD=W1p[k*65+s+48];
        const u64* ap=(const u64*)(L+LH1+k*20) + 5*half;
        #pragma unroll
        for (int q=0;q<5;q++){ u64 av=ap[q];
            fma2(acc[q],wA,av); fma2(acc[5+q],wB,av);
            fma2(acc[10+q],wC,av); fma2(acc[15+q],wD,av); }
    }
    #pragma unroll
    for (int v=0; v<20; v++) acc[v] = tanh2(acc[v]);

    // H: z reduction, enc, prior
    {
        u64 zp[5];
        #pragma unroll
        for (int q=0;q<5;q++) zp[q]=0ull;
        #pragma unroll
        for (int i=0;i<4;i++){ u64 w2p=W2p[s+16*i];
            #pragma unroll
            for (int q=0;q<5;q++) fma2(zp[q], w2p, acc[i*5+q]); }
        #pragma unroll
        for (int m=1;m<16;m<<=1){
            #pragma unroll
            for (int q=0;q<5;q++) zp[q]=add2(zp[q], __shfl_xor_sync(0xffffffffu, zp[q], m));
        }
        if (s==0){ u64 b2p=pk2(sm[OMISC]); u64* zz=(u64*)(L+LZ) + 5*half;
            #pragma unroll
            for (int q=0;q<5;q++) zz[q]=add2(zp[q],b2p); }
    }
    __syncwarp();
    if (t < NN){
        float enc = tanhfst(L[LZ+t]);
        float e = enc*enc + EPSF;
        float Rm = L[LNEWR+t] - e;
        float P=0.f, D=0.f;
        #pragma unroll
        for (int j=0;j<3;j++){
            float a=sm[OMISC+1+j], p=sm[OMISC+4+j];
            float tt = ex2a(-p * lg2a(a*Rm));
            P += tt; D += p*tt;
        }
        L[LP+t]=P; L[LGPRE+t]=D/Rm; L[LENC+t]=enc;
    }
    __syncwarp();
    if (t==0){
        float S=0.f, F=0.f;
        #pragma unroll
        for (int n=0;n<NN;n++){ S+=L[LP+n]; F+=L[LFCR+n]; }
        L[LSC]=S; L[LSC+1]=F;
    }
    __syncwarp();
    if (t < NN){
        float enc=L[LENC+t];
        L[LGZ+t] = L[LSC+1]*L[LGPRE+t]*2.f*enc*(1.f-enc*enc);
        if (wr) out[(size_t)6*B + (size_t)batch*NN + t] = L[LSC]*L[LFCR+t];
    }
    __syncwarp();
    // I: ga2 from register h2 -> smem (LGT over dead feat)
    {
        const u64 SGN = 0x8000000080000000ULL;
        u64 one2 = pk2(1.0f);
        #pragma unroll
        for (int i=0;i<4;i++){
            u64 w2p=W2p[s+16*i];
            u64* gr=(u64*)(L+LGT+(s+16*i)*20) + 5*half;
            #pragma unroll
            for (int q=0;q<5;q++){
                u64 h2v=acc[i*5+q];
                u64 d = fma2o(h2v ^ SGN, h2v, one2);
                u64 gzq = *(const u64*)(L+LGZ+2*(5*half+q));
                gr[q] = mul2(mul2(gzq,w2p), d);
            }
        }
    }
    __syncwarp();
    // J: GEMM3 (gh1 = ga2 @ W1^T), ga1 overwrites LH1
    #pragma unroll
    for (int v=0; v<20; v++) acc[v]=0ull;
    #pragma unroll 8
    for (int k=0;k<64;k++){
        u64 wA=W1p[ s      *65+k], wB=W1p[(s+16)*65+k];
        u64 wC=W1p[(s+32)*65+k],   wD=W1p[(s+48)*65+k];
        const u64* ap=(const u64*)(L+LGT+k*20) + 5*half;
        #pragma unroll
        for (int q=0;q<5;q++){ u64 av=ap[q];
            fma2(acc[q],wA,av); fma2(acc[5+q],wB,av);
            fma2(acc[10+q],wC,av); fma2(acc[15+q],wD,av); }
    }
    {
        const u64 SGN = 0x8000000080000000ULL;
        u64 one2 = pk2(1.0f);
        #pragma unroll
        for (int i=0;i<4;i++){
            u64* hr=(u64*)(L+LH1+(s+16*i)*20) + 5*half;
            #pragma unroll
            for (int q=0;q<5;q++){
                u64 h1v=hr[q];
                u64 d = fma2o(h1v ^ SGN, h1v, one2);
                hr[q] = mul2(acc[i*5+q], d);
            }
        }
    }
    __syncwarp();
    // K: GEMM4 gfeat[n][i] = sum_k ga1[k][n] W0[i][k]  (LGF over dead LGT)
    if (s < 15){
        u64 a4[5];
        #pragma unroll
        for (int q=0;q<5;q++) a4[q]=0ull;
        #pragma unroll 8
        for (int k=0;k<64;k++){
            u64 w=W0p[s*65+k];
            const u64* ap=(const u64*)(L+LH1+k*20) + 5*half;
            #pragma unroll
            for (int q=0;q<5;q++) fma2(a4[q],w,ap[q]);
        }
        #pragma unroll
        for (int q=0;q<5;q++){
            float lo,hi; upk(a4[q],lo,hi);
            int n0 = 10*half + 2*q;
            L[LGF+n0*16+s]=lo; L[LGF+(n0+1)*16+s]=hi;
        }
    }
    __syncwarp();
    // L: force, gO (aliases dead LFCR), torque
    if (t < 3){
        float f=0.f; const float* O=L+LSO;
        for (int n=0;n<NN;n++){
            const float* g=L+LGF+n*16; const float* NO=L+LNOR+n*9;
            f += g[0]*O[t*3]+g[1]*O[t*3+1]+g[2]*O[t*3+2];
            f += g[3]*NO[t*3]+g[4]*NO[t*3+1]+g[5]*NO[t*3+2];
        }
        if (wr) out[(size_t)batch*3+t]=f;
    }
    if (t >= 4 && t < 13){
        int a=(t-4)/3, bb=(t-4)%3; float g2=0.f;
        for (int n=0;n<NN;n++){
            const float* g=L+LGF+n*16; const float* NO=L+LNOR+n*9;
            g2 += L[LNDN+n*3+a]*g[bb];
            g2 += g[6+3*bb+0]*NO[a*3+0]+g[6+3*bb+1]*NO[a*3+1]+g[6+3*bb+2]*NO[a*3+2];
        }
        L[LGO+a*3+bb]=g2;
    }
    __syncwarp();
    if (t==0 && wr){
        const float* gO=L+LGO; const float* O=L+LSO;
        float tx=0.f,ty=0.f,tz=0.f;
        #pragma unroll
        for (int c=0;c<3;c++){
            float u0=gO[c],u1=gO[3+c],u2=gO[6+c];
            float v0=O[c], v1=O[3+c], v2=O[6+c];
            tx += u1*v2-u2*v1; ty += u2*v0-u0*v2; tz += u0*v1-u1*v0;
        }
        out[(size_t)3*B+(size_t)batch*3+0]=tx;
        out[(size_t)3*B+(size_t)batch*3+1]=ty;
        out[(size_t)3*B+(size_t)batch*3+2]=tz;
    }
}

extern "C" void kernel_launch(void* const* d_in, const int* in_sizes, int n_in,
                              void* d_out, int out_size) {
    const float* dr  = (const float*)d_in[0];
    const float* ori = (const float*)d_in[1];
    const float* nor = (const float*)d_in[2];
    const float* W0  = (const float*)d_in[3];
    const float* b0  = (const float*)d_in[4];
    const float* W1  = (const float*)d_in[5];
    const float* b1  = (const float*)d_in[6];
    const float* W2  = (const float*)d_in[7];
    const float* b2  = (const float*)d_in[8];
    const float* f1  = (const float*)d_in[9];
    const float* f2  = (const float*)d_in[10];
    float* out = (float*)d_out;

    int B = in_sizes[0] / (NBC * 3);
    int blocks = (B + LPB - 1) / LPB;
    size_t shmem = (size_t)SMEM_FLOATS * sizeof(float);
    cudaFuncSetAttribute(ep_kernel, cudaFuncAttributeMaxDynamicSharedMemorySize, (int)shmem);
    ep_kernel<<<blocks, TPB, shmem>>>(dr, ori, nor, W0, b0, W1, b1, W2, b2, f1, f2, out, B);
}

// round 9
// speedup vs baseline: 1.0664x; 1.0664x over previous
#include <cuda_runtime.h>
#include <math.h>

#define EPSF 1e-8f
#define NBC 64
#define NN 20
#define LPB 19
#define TPB (LPB*32)

// weights region (floats)
static constexpr int OW0 = 0, OW1 = 976, OW2 = 5136, OB0 = 5200, OB1 = 5264, OMISC = 5328, WFL = 5336;
// per-lane offsets (floats). NOR is NOT staged (read from gmem).
// front scalars:
static constexpr int LNDN = 0, LNEWR = 60, LP = 60, LFCR = 80, LGO = 80, LSO = 100,
    LZ = 112, LENC = LZ, LGZ = 132, LGPRE = 152, LSC = 172, LSELF = 176;
// mid region (1280 fl) lifetime-aliased: DRW/RR -> FEAT -> GT -> GF
static constexpr int LDRW = 200, LRR = 392, LFEAT = 200, LGT = 200, LGF = 200;
static constexpr int LH1 = 1480, LANE_F = 2760;
static constexpr int SMEM_FLOATS = WFL + LPB * LANE_F;   // 57776+? = 5336+52440 = 57776 fl = 231104 B

typedef unsigned long long u64;
__device__ __forceinline__ u64 pk2(float a){ u64 r; asm("mov.b64 %0, {%1, %1};":"=l"(r):"f"(a)); return r; }
__device__ __forceinline__ u64 pk(float a,float b){ u64 r; asm("mov.b64 %0, {%1, %2};":"=l"(r):"f"(a),"f"(b)); return r; }
__device__ __forceinline__ void upk(u64 v,float&a,float&b){ asm("mov.b64 {%0, %1}, %2;":"=f"(a),"=f"(b):"l"(v)); }
__device__ __forceinline__ void fma2(u64&c,u64 a,u64 b){ asm("fma.rn.f32x2 %0, %1, %2, %0;":"+l"(c):"l"(a),"l"(b)); }
__device__ __forceinline__ u64 fma2o(u64 a,u64 b,u64 c){ u64 d; asm("fma.rn.f32x2 %0, %1, %2, %3;":"=l"(d):"l"(a),"l"(b),"l"(c)); return d; }
__device__ __forceinline__ u64 mul2(u64 a,u64 b){ u64 d; asm("mul.rn.f32x2 %0, %1, %2;":"=l"(d):"l"(a),"l"(b)); return d; }
__device__ __forceinline__ u64 add2(u64 a,u64 b){ u64 d; asm("add.rn.f32x2 %0, %1, %2;":"=l"(d):"l"(a),"l"(b)); return d; }
__device__ __forceinline__ float ex2a(float x){ float r; asm("ex2.approx.f32 %0, %1;":"=f"(r):"f"(x)); return r; }
__device__ __forceinline__ float lg2a(float x){ float r; asm("lg2.approx.f32 %0, %1;":"=f"(r):"f"(x)); return r; }
__device__ __forceinline__ float rcpa(float x){ float r; asm("rcp.approx.f32 %0, %1;":"=f"(r):"f"(x)); return r; }
__device__ __forceinline__ float tanhfst(float x){
    float e = ex2a(x * 2.885390082f);
    return fmaf(-2.0f, rcpa(e + 1.0f), 1.0f);
}
__device__ __forceinline__ u64 tanh2(u64 v){
    u64 xe = mul2(v, pk2(2.885390082f));
    float a,b; upk(xe,a,b);
    u64 e = pk(ex2a(a), ex2a(b));
    u64 r = add2(e, pk2(1.0f));
    float c,d; upk(r,c,d);
    u64 rc = pk(rcpa(c), rcpa(d));
    return fma2o(rc, pk2(-2.0f), pk2(1.0f));
}

__global__ __launch_bounds__(TPB, 1)
void ep_kernel(const float* __restrict__ dr, const float* __restrict__ orientation,
               const float* __restrict__ n_or,
               const float* __restrict__ W0, const float* __restrict__ b0,
               const float* __restrict__ W1, const float* __restrict__ b1,
               const float* __restrict__ W2, const float* __restrict__ b2,
               const float* __restrict__ f1, const float* __restrict__ f2,
               float* __restrict__ out, int B)
{
    extern __shared__ float sm[];
    const int tid = threadIdx.x;
    for (int idx = tid; idx < 960; idx += TPB)  { int i=idx>>6, j=idx&63; sm[OW0+i*65+j]=W0[idx]; }
    for (int idx = tid; idx < 4096; idx += TPB) { int k=idx>>6, j=idx&63; sm[OW1+k*65+j]=W1[idx]; }
    if (tid < 64) { sm[OW2+tid]=W2[tid]; sm[OB0+tid]=b0[tid]; sm[OB1+tid]=b1[tid]; }
    if (tid == 0) {
        sm[OMISC] = b2[0];
        #pragma unroll
        for (int j = 0; j < 3; j++) {
            float a=f1[j]; sm[OMISC+1+j]=a*a+EPSF;
            float p=f2[j]; sm[OMISC+4+j]=p*p+EPSF;
        }
    }
    __syncthreads();

    const int li = tid >> 5, t = tid & 31;
    const int s = t & 15, half = t >> 4;
    const int batch0 = blockIdx.x * LPB + li;
    const bool wr = batch0 < B;
    const int batch = wr ? batch0 : 0;
    float* L = sm + WFL + li * LANE_F;
    int* selp = (int*)(L + LSELF);
    const float* NOB = n_or + (size_t)batch * NBC * 9;   // per-batch n_or base

    // A: stage dr + orientation
    {
        const float4* src = (const float4*)(dr + (size_t)batch * 192);
        float4* dst = (float4*)(L + LDRW);
        dst[t] = src[t];
        if (t < 16) dst[t+32] = src[t+32];
        if (t < 9) L[LSO+t] = orientation[(size_t)batch*9 + t];
    }
    __syncwarp();
    // B: radii
    #pragma unroll
    for (int c = 0; c < 2; c++) {
        int u = 2*t+c;
        float x=L[LDRW+u*3]+EPSF, y=L[LDRW+u*3+1]+EPSF, z=L[LDRW+u*3+2]+EPSF;
        L[LRR+u] = sqrtf(x*x+y*y+z*z);
    }
    __syncwarp();
    // C: stable rank -> sel indices (front region, survives mid-region aliasing)
    {
        float Ru[2]; int rk[2];
        #pragma unroll
        for (int c=0;c<2;c++){ Ru[c]=L[LRR+2*t+c]; rk[c]=0; }
        const float4* R4 = (const float4*)(L + LRR);
        #pragma unroll 4
        for (int v4=0; v4<16; v4++){
            float4 rv = R4[v4]; int v = 4*v4;
            #pragma unroll
            for (int c=0;c<2;c++){
                int u = 2*t+c;
                rk[c] += (rv.x<Ru[c])||(rv.x==Ru[c]&&v  <u);
                rk[c] += (rv.y<Ru[c])||(rv.y==Ru[c]&&v+1<u);
                rk[c] += (rv.z<Ru[c])||(rv.z==Ru[c]&&v+2<u);
                rk[c] += (rv.w<Ru[c])||(rv.w==Ru[c]&&v+3<u);
            }
        }
        #pragma unroll
        for (int c=0;c<2;c++) if (rk[c] < NN) selp[rk[c]] = 2*t+c;
    }
    __syncwarp();
    // D: gather top-20 (no NOR staging)
    if (t < NN) {
        int u = selp[t];
        float Rv = L[LRR+u];
        L[LNEWR+t] = Rv;
        float inv = 1.0f / Rv;
        L[LNDN+t*3+0] = (L[LDRW+u*3+0]+EPSF)*inv;
        L[LNDN+t*3+1] = (L[LDRW+u*3+1]+EPSF)*inv;
        L[LNDN+t*3+2] = (L[LDRW+u*3+2]+EPSF)*inv;
        L[LFCR+t] = (Rv > 4.8f) ? 0.0f : (0.5f*cospif(Rv*(1.0f/4.8f)) + 0.5f);
    }
    __syncwarp();
    // E: features featT[i][n], stride 20 (over dead DRW/RR); NOR from gmem
    {
        int n = (t * 0x8889) >> 19;
        int i = t - n*15;
        #pragma unroll
        for (int it = 0; it < 10; it++) {
            int p = t + 32*it;
            if (p < 300) {
                const float* nd = L+LNDN+n*3; const float* O = L+LSO;
                const float* NO = NOB + selp[n]*9;
                float v;
                if (i < 3)      v = nd[0]*O[i]   + nd[1]*O[3+i]   + nd[2]*O[6+i];
                else if (i < 6){ int h=i-3; v = nd[0]*NO[h] + nd[1]*NO[3+h] + nd[2]*NO[6+h]; }
                else { int l=(i-6)/3, m=(i-6)%3; v = O[l]*NO[m] + O[3+l]*NO[3+m] + O[6+l]*NO[6+m]; }
                L[LFEAT + i*20 + n] = v;
            }
            n += 2; i += 2;
            if (i >= 15) { i -= 15; n += 1; }
        }
    }
    __syncwarp();

    u64 acc[20];
    // F: GEMM1 -> h1
    #pragma unroll
    for (int i=0;i<4;i++){ u64 bb=pk2(sm[OB0+s+16*i]);
        #pragma unroll
        for (int q=0;q<5;q++) acc[i*5+q]=bb; }
    #pragma unroll 5
    for (int k=0;k<15;k++){
        u64 wA=pk2(sm[OW0+k*65+s]),    wB=pk2(sm[OW0+k*65+s+16]);
        u64 wC=pk2(sm[OW0+k*65+s+32]), wD=pk2(sm[OW0+k*65+s+48]);
        const u64* ap=(const u64*)(L+LFEAT+k*20) + 5*half;
        #pragma unroll
        for (int q=0;q<5;q++){ u64 av=ap[q];
            fma2(acc[q],wA,av); fma2(acc[5+q],wB,av);
            fma2(acc[10+q],wC,av); fma2(acc[15+q],wD,av); }
    }
    #pragma unroll
    for (int i=0;i<4;i++){
        u64* hr=(u64*)(L+LH1+(s+16*i)*20) + 5*half;
        #pragma unroll
        for (int q=0;q<5;q++) hr[q]=tanh2(acc[i*5+q]);
    }
    __syncwarp();
    // G: GEMM2 -> h2 (registers only)
    #pragma unroll
    for (int i=0;i<4;i++){ u64 bb=pk2(sm[OB1+s+16*i]);
        #pragma unroll
        for (int q=0;q<5;q++) acc[i*5+q]=bb; }
    #pragma unroll 8
    for (int k=0;k<64;k++){
        u64 wA=pk2(sm[OW1+k*65+s]),    wB=pk2(sm[OW1+k*65+s+16]);
        u64 wC=pk2(sm[OW1+k*65+s+32]), wD=pk2(sm[OW1+k*65+s+48]);
        const u64* ap=(const u64*)(L+LH1+k*20) + 5*half;
        #pragma unroll
        for (int q=0;q<5;q++){ u64 av=ap[q];
            fma2(acc[q],wA,av); fma2(acc[5+q],wB,av);
            fma2(acc[10+q],wC,av); fma2(acc[15+q],wD,av); }
    }
    #pragma unroll
    for (int v=0; v<20; v++) acc[v] = tanh2(acc[v]);

    // H: z reduction, enc, prior
    {
        u64 zp[5];
        #pragma unroll
        for (int q=0;q<5;q++) zp[q]=0ull;
        #pragma unroll
        for (int i=0;i<4;i++){ u64 w2p=pk2(sm[OW2+s+16*i]);
            #pragma unroll
            for (int q=0;q<5;q++) fma2(zp[q], w2p, acc[i*5+q]); }
        #pragma unroll
        for (int m=1;m<16;m<<=1){
            #pragma unroll
            for (int q=0;q<5;q++) zp[q]=add2(zp[q], __shfl_xor_sync(0xffffffffu, zp[q], m));
        }
        if (s==0){ u64 b2p=pk2(sm[OMISC]); u64* zz=(u64*)(L+LZ) + 5*half;
            #pragma unroll
            for (int q=0;q<5;q++) zz[q]=add2(zp[q],b2p); }
    }
    __syncwarp();
    if (t < NN){
        float enc = tanhfst(L[LZ+t]);
        float e = enc*enc + EPSF;
        float Rm = L[LNEWR+t] - e;        // read NEWR, then LP aliases (same thread)
        float P=0.f, D=0.f;
        #pragma unroll
        for (int j=0;j<3;j++){
            float a=sm[OMISC+1+j], p=sm[OMISC+4+j];
            float tt = ex2a(-p * lg2a(a*Rm));
            P += tt; D += p*tt;
        }
        L[LP+t]=P; L[LGPRE+t]=D/Rm; L[LENC+t]=enc;
    }
    __syncwarp();
    if (t==0){
        float S=0.f, F=0.f;
        #pragma unroll
        for (int n=0;n<NN;n++){ S+=L[LP+n]; F+=L[LFCR+n]; }
        L[LSC]=S; L[LSC+1]=F;
    }
    __syncwarp();
    if (t < NN){
        float enc=L[LENC+t];
        L[LGZ+t] = L[LSC+1]*L[LGPRE+t]*2.f*enc*(1.f-enc*enc);
        if (wr) out[(size_t)6*B + (size_t)batch*NN + t] = L[LSC]*L[LFCR+t];
    }
    __syncwarp();
    // I: ga2 from register h2 -> smem (LGT over dead feat)
    {
        const u64 SGN = 0x8000000080000000ULL;
        u64 one2 = pk2(1.0f);
        #pragma unroll
        for (int i=0;i<4;i++){
            u64 w2p=pk2(sm[OW2+s+16*i]);
            u64* gr=(u64*)(L+LGT+(s+16*i)*20) + 5*half;
            #pragma unroll
            for (int q=0;q<5;q++){
                u64 h2v=acc[i*5+q];
                u64 d = fma2o(h2v ^ SGN, h2v, one2);
                u64 gzq = *(const u64*)(L+LGZ+2*(5*half+q));
                gr[q] = mul2(mul2(gzq,w2p), d);
            }
        }
    }
    __syncwarp();
    // J: GEMM3 (gh1 = ga2 @ W1^T), ga1 overwrites LH1
    #pragma unroll
    for (int v=0; v<20; v++) acc[v]=0ull;
    #pragma unroll 8
    for (int k=0;k<64;k++){
        u64 wA=pk2(sm[OW1+ s      *65+k]), wB=pk2(sm[OW1+(s+16)*65+k]);
        u64 wC=pk2(sm[OW1+(s+32)*65+k]),   wD=pk2(sm[OW1+(s+48)*65+k]);
        const u64* ap=(const u64*)(L+LGT+k*20) + 5*half;
        #pragma unroll
        for (int q=0;q<5;q++){ u64 av=ap[q];
            fma2(acc[q],wA,av); fma2(acc[5+q],wB,av);
            fma2(acc[10+q],wC,av); fma2(acc[15+q],wD,av); }
    }
    {
        const u64 SGN = 0x8000000080000000ULL;
        u64 one2 = pk2(1.0f);
        #pragma unroll
        for (int i=0;i<4;i++){
            u64* hr=(u64*)(L+LH1+(s+16*i)*20) + 5*half;
            #pragma unroll
            for (int q=0;q<5;q++){
                u64 h1v=hr[q];
                u64 d = fma2o(h1v ^ SGN, h1v, one2);
                hr[q] = mul2(acc[i*5+q], d);
            }
        }
    }
    __syncwarp();
    // K: GEMM4 gfeat[n][i] = sum_k ga1[k][n] W0[i][k]  (LGF over dead LGT)
    if (s < 15){
        u64 a4[5];
        #pragma unroll
        for (int q=0;q<5;q++) a4[q]=0ull;
        #pragma unroll 8
        for (int k=0;k<64;k++){
            u64 w=pk2(sm[OW0+s*65+k]);
            const u64* ap=(const u64*)(L+LH1+k*20) + 5*half;
            #pragma unroll
            for (int q=0;q<5;q++) fma2(a4[q],w,ap[q]);
        }
        #pragma unroll
        for (int q=0;q<5;q++){
            float lo,hi; upk(a4[q],lo,hi);
            int n0 = 10*half + 2*q;
            L[LGF+n0*16+s]=lo; L[LGF+(n0+1)*16+s]=hi;
        }
    }
    __syncwarp();
    // L: force, gO (aliases dead LFCR), torque; NOR from gmem
    if (t < 3){
        float f=0.f; const float* O=L+LSO;
        #pragma unroll 4
        for (int n=0;n<NN;n++){
            const float* g=L+LGF+n*16;
            const float* NO = NOB + selp[n]*9;
            f += g[0]*O[t*3]+g[1]*O[t*3+1]+g[2]*O[t*3+2];
            f += g[3]*NO[t*3]+g[4]*NO[t*3+1]+g[5]*NO[t*3+2];
        }
        if (wr) out[(size_t)batch*3+t]=f;
    }
    if (t >= 4 && t < 13){
        int a=(t-4)/3, bb=(t-4)%3; float g2=0.f;
        #pragma unroll 4
        for (int n=0;n<NN;n++){
            const float* g=L+LGF+n*16;
            const float* NO = NOB + selp[n]*9;
            g2 += L[LNDN+n*3+a]*g[bb];
            g2 += g[6+3*bb+0]*NO[a*3+0]+g[6+3*bb+1]*NO[a*3+1]+g[6+3*bb+2]*NO[a*3+2];
        }
        L[LGO+a*3+bb]=g2;
    }
    __syncwarp();
    if (t==0 && wr){
        const float* gO=L+LGO; const float* O=L+LSO;
        float tx=0.f,ty=0.f,tz=0.f;
        #pragma unroll
        for (int c=0;c<3;c++){
            float u0=gO[c],u1=gO[3+c],u2=gO[6+c];
            float v0=O[c], v1=O[3+c], v2=O[6+c];
            tx += u1*v2-u2*v1; ty += u2*v0-u0*v2; tz += u0*v1-u1*v0;
        }
        out[(size_t)3*B+(size_t)batch*3+0]=tx;
        out[(size_t)3*B+(size_t)batch*3+1]=ty;
        out[(size_t)3*B+(size_t)batch*3+2]=tz;
    }
}

extern "C" void kernel_launch(void* const* d_in, const int* in_sizes, int n_in,
                              void* d_out, int out_size) {
    const float* dr  = (const float*)d_in[0];
    const float* ori = (const float*)d_in[1];
    const float* nor = (const float*)d_in[2];
    const float* W0  = (const float*)d_in[3];
    const float* b0  = (const float*)d_in[4];
    const float* W1  = (const float*)d_in[5];
    const float* b1  = (const float*)d_in[6];
    const float* W2  = (const float*)d_in[7];
    const float* b2  = (const float*)d_in[8];
    const float* f1  = (const float*)d_in[9];
    const float* f2  = (const float*)d_in[10];
    float* out = (float*)d_out;

    int B = in_sizes[0] / (NBC * 3);
    int blocks = (B + LPB - 1) / LPB;
    size_t shmem = (size_t)SMEM_FLOATS * sizeof(float);
    cudaFuncSetAttribute(ep_kernel, cudaFuncAttributeMaxDynamicSharedMemorySize, (int)shmem);
    ep_kernel<<<blocks, TPB, shmem>>>(dr, ori, nor, W0, b0, W1, b1, W2, b2, f1, f2, out, B);
}

// round 10
// speedup vs baseline: 1.1883x; 1.1143x over previous
#include <cuda_runtime.h>
#include <math.h>

#define EPSF 1e-8f
#define NBC 64
#define NN 20
#define LPB 18
#define TPB (LPB*32)

// weights region (floats), row stride 66 (8B-pair alignment for backward reads)
static constexpr int OW0 = 0, OW1 = 992, OW2 = 5216, OB0 = 5280, OB1 = 5344, OMISC = 5408, WFL = 5416;
// per-lane offsets (floats); mid region lifetime-aliased: DRW/RR/SEL -> FEAT -> GT -> GF
static constexpr int LNDN = 0, LNOR = 60, LNEWR = 240, LP = 240, LFCR = 260, LGO = 260,
    LSO = 280, LZ = 290, LENC = LZ, LGZ = 310, LGPRE = 330, LSC = 350,
    LDRW = 352, LRR = 544, LSEL = 608, LFEAT = 352, LGT = 352, LGF = 352,
    LH1 = 1632, LANE_F = 2912;
static constexpr int SMEM_FLOATS = WFL + LPB * LANE_F;   // 57832 fl = 231328 B

typedef unsigned long long u64;
__device__ __forceinline__ u64 pk2(float a){ u64 r; asm("mov.b64 %0, {%1, %1};":"=l"(r):"f"(a)); return r; }
__device__ __forceinline__ u64 pk(float a,float b){ u64 r; asm("mov.b64 %0, {%1, %2};":"=l"(r):"f"(a),"f"(b)); return r; }
__device__ __forceinline__ void upk(u64 v,float&a,float&b){ asm("mov.b64 {%0, %1}, %2;":"=f"(a),"=f"(b):"l"(v)); }
__device__ __forceinline__ void fma2(u64&c,u64 a,u64 b){ asm("fma.rn.f32x2 %0, %1, %2, %0;":"+l"(c):"l"(a),"l"(b)); }
__device__ __forceinline__ u64 fma2o(u64 a,u64 b,u64 c){ u64 d; asm("fma.rn.f32x2 %0, %1, %2, %3;":"=l"(d):"l"(a),"l"(b),"l"(c)); return d; }
__device__ __forceinline__ u64 mul2(u64 a,u64 b){ u64 d; asm("mul.rn.f32x2 %0, %1, %2;":"=l"(d):"l"(a),"l"(b)); return d; }
__device__ __forceinline__ u64 add2(u64 a,u64 b){ u64 d; asm("add.rn.f32x2 %0, %1, %2;":"=l"(d):"l"(a),"l"(b)); return d; }
__device__ __forceinline__ float ex2a(float x){ float r; asm("ex2.approx.f32 %0, %1;":"=f"(r):"f"(x)); return r; }
__device__ __forceinline__ float lg2a(float x){ float r; asm("lg2.approx.f32 %0, %1;":"=f"(r):"f"(x)); return r; }
__device__ __forceinline__ float rcpa(float x){ float r; asm("rcp.approx.f32 %0, %1;":"=f"(r):"f"(x)); return r; }
__device__ __forceinline__ float tanhfst(float x){
    float e = ex2a(x * 2.885390082f);
    return fmaf(-2.0f, rcpa(e + 1.0f), 1.0f);
}
__device__ __forceinline__ u64 tanh2(u64 v){
    u64 xe = mul2(v, pk2(2.885390082f));
    float a,b; upk(xe,a,b);
    u64 e = pk(ex2a(a), ex2a(b));
    u64 r = add2(e, pk2(1.0f));
    float c,d; upk(r,c,d);
    u64 rc = pk(rcpa(c), rcpa(d));
    return fma2o(rc, pk2(-2.0f), pk2(1.0f));
}

__global__ __launch_bounds__(TPB, 1)
void ep_kernel(const float* __restrict__ dr, const float* __restrict__ orientation,
               const float* __restrict__ n_or,
               const float* __restrict__ W0, const float* __restrict__ b0,
               const float* __restrict__ W1, const float* __restrict__ b1,
               const float* __restrict__ W2, const float* __restrict__ b2,
               const float* __restrict__ f1, const float* __restrict__ f2,
               float* __restrict__ out, int B)
{
    extern __shared__ float sm[];
    const int tid = threadIdx.x;
    for (int idx = tid; idx < 960; idx += TPB)  { int i=idx>>6, j=idx&63; sm[OW0+i*66+j]=W0[idx]; }
    for (int idx = tid; idx < 4096; idx += TPB) { int k=idx>>6, j=idx&63; sm[OW1+k*66+j]=W1[idx]; }
    if (tid < 64) { sm[OW2+tid]=W2[tid]; sm[OB0+tid]=b0[tid]; sm[OB1+tid]=b1[tid]; }
    if (tid == 0) {
        sm[OMISC] = b2[0];
        #pragma unroll
        for (int j = 0; j < 3; j++) {
            float a=f1[j]; sm[OMISC+1+j]=a*a+EPSF;
            float p=f2[j]; sm[OMISC+4+j]=p*p+EPSF;
        }
    }
    __syncthreads();

    const int li = tid >> 5, t = tid & 31;
    const int s = t & 15, half = t >> 4;
    const int batch0 = blockIdx.x * LPB + li;
    const bool wr = batch0 < B;
    const int batch = wr ? batch0 : 0;
    float* L = sm + WFL + li * LANE_F;
    int* selp = (int*)(L + LSEL);

    // A: stage dr + orientation
    {
        const float4* src = (const float4*)(dr + (size_t)batch * 192);
        float4* dst = (float4*)(L + LDRW);
        dst[t] = src[t];
        if (t < 16) dst[t+32] = src[t+32];
        if (t < 9) L[LSO+t] = orientation[(size_t)batch*9 + t];
    }
    __syncwarp();
    // B: radii
    #pragma unroll
    for (int c = 0; c < 2; c++) {
        int u = 2*t+c;
        float x=L[LDRW+u*3]+EPSF, y=L[LDRW+u*3+1]+EPSF, z=L[LDRW+u*3+2]+EPSF;
        L[LRR+u] = sqrtf(x*x+y*y+z*z);
    }
    __syncwarp();
    // C: stable rank
    {
        float Ru[2]; int rk[2];
        #pragma unroll
        for (int c=0;c<2;c++){ Ru[c]=L[LRR+2*t+c]; rk[c]=0; }
        const float4* R4 = (const float4*)(L + LRR);
        #pragma unroll 4
        for (int v4=0; v4<16; v4++){
            float4 rv = R4[v4]; int v = 4*v4;
            #pragma unroll
            for (int c=0;c<2;c++){
                int u = 2*t+c;
                rk[c] += (rv.x<Ru[c])||(rv.x==Ru[c]&&v  <u);
                rk[c] += (rv.y<Ru[c])||(rv.y==Ru[c]&&v+1<u);
                rk[c] += (rv.z<Ru[c])||(rv.z==Ru[c]&&v+2<u);
                rk[c] += (rv.w<Ru[c])||(rv.w==Ru[c]&&v+3<u);
            }
        }
        #pragma unroll
        for (int c=0;c<2;c++) if (rk[c] < NN) selp[rk[c]] = 2*t+c;
    }
    __syncwarp();
    // D: gather top-20 (NOR staged in smem)
    if (t < NN) {
        int u = selp[t];
        float Rv = L[LRR+u];
        L[LNEWR+t] = Rv;
        float inv = 1.0f / Rv;
        L[LNDN+t*3+0] = (L[LDRW+u*3+0]+EPSF)*inv;
        L[LNDN+t*3+1] = (L[LDRW+u*3+1]+EPSF)*inv;
        L[LNDN+t*3+2] = (L[LDRW+u*3+2]+EPSF)*inv;
        L[LFCR+t] = (Rv > 4.8f) ? 0.0f : (0.5f*cospif(Rv*(1.0f/4.8f)) + 0.5f);
        const float* np_ = n_or + ((size_t)batch*NBC + u)*9;
        #pragma unroll
        for (int e = 0; e < 9; e++) L[LNOR+t*9+e] = np_[e];
    }
    __syncwarp();
    // E: features featT[i][n], stride 20 (over dead DRW/RR)
    {
        int n = (t * 0x8889) >> 19;
        int i = t - n*15;
        #pragma unroll
        for (int it = 0; it < 10; it++) {
            int p = t + 32*it;
            if (p < 300) {
                const float* nd = L+LNDN+n*3; const float* NO = L+LNOR+n*9; const float* O = L+LSO;
                float v;
                if (i < 3)      v = nd[0]*O[i]   + nd[1]*O[3+i]   + nd[2]*O[6+i];
                else if (i < 6){ int h=i-3; v = nd[0]*NO[h] + nd[1]*NO[3+h] + nd[2]*NO[6+h]; }
                else { int l=(i-6)/3, m=(i-6)%3; v = O[l]*NO[m] + O[3+l]*NO[3+m] + O[6+l]*NO[6+m]; }
                L[LFEAT + i*20 + n] = v;
            }
            n += 2; i += 2;
            if (i >= 15) { i -= 15; n += 1; }
        }
    }
    __syncwarp();

    u64 acc[20];
    // F: GEMM1 -> h1
    #pragma unroll
    for (int i=0;i<4;i++){ u64 bb=pk2(sm[OB0+s+16*i]);
        #pragma unroll
        for (int q=0;q<5;q++) acc[i*5+q]=bb; }
    #pragma unroll 5
    for (int k=0;k<15;k++){
        u64 wA=pk2(sm[OW0+k*66+s]),    wB=pk2(sm[OW0+k*66+s+16]);
        u64 wC=pk2(sm[OW0+k*66+s+32]), wD=pk2(sm[OW0+k*66+s+48]);
        const u64* ap=(const u64*)(L+LFEAT+k*20) + 5*half;
        #pragma unroll
        for (int q=0;q<5;q++){ u64 av=ap[q];
            fma2(acc[q],wA,av); fma2(acc[5+q],wB,av);
            fma2(acc[10+q],wC,av); fma2(acc[15+q],wD,av); }
    }
    #pragma unroll
    for (int i=0;i<4;i++){
        u64* hr=(u64*)(L+LH1+(s+16*i)*20) + 5*half;
        #pragma unroll
        for (int q=0;q<5;q++) hr[q]=tanh2(acc[i*5+q]);
    }
    __syncwarp();
    // G: GEMM2 -> h2 (registers only)
    #pragma unroll
    for (int i=0;i<4;i++){ u64 bb=pk2(sm[OB1+s+16*i]);
        #pragma unroll
        for (int q=0;q<5;q++) acc[i*5+q]=bb; }
    #pragma unroll 8
    for (int k=0;k<64;k++){
        u64 wA=pk2(sm[OW1+k*66+s]),    wB=pk2(sm[OW1+k*66+s+16]);
        u64 wC=pk2(sm[OW1+k*66+s+32]), wD=pk2(sm[OW1+k*66+s+48]);
        const u64* ap=(const u64*)(L+LH1+k*20) + 5*half;
        #pragma unroll
        for (int q=0;q<5;q++){ u64 av=ap[q];
            fma2(acc[q],wA,av); fma2(acc[5+q],wB,av);
            fma2(acc[10+q],wC,av); fma2(acc[15+q],wD,av); }
    }
    #pragma unroll
    for (int v=0; v<20; v++) acc[v] = tanh2(acc[v]);

    // H: z reduction, enc, prior
    {
        u64 zp[5];
        #pragma unroll
        for (int q=0;q<5;q++) zp[q]=0ull;
        #pragma unroll
        for (int i=0;i<4;i++){ u64 w2p=pk2(sm[OW2+s+16*i]);
            #pragma unroll
            for (int q=0;q<5;q++) fma2(zp[q], w2p, acc[i*5+q]); }
        #pragma unroll
        for (int m=1;m<16;m<<=1){
            #pragma unroll
            for (int q=0;q<5;q++) zp[q]=add2(zp[q], __shfl_xor_sync(0xffffffffu, zp[q], m));
        }
        if (s==0){ u64 b2p=pk2(sm[OMISC]); u64* zz=(u64*)(L+LZ) + 5*half;
            #pragma unroll
            for (int q=0;q<5;q++) zz[q]=add2(zp[q],b2p); }
    }
    __syncwarp();
    if (t < NN){
        float enc = tanhfst(L[LZ+t]);
        float e = enc*enc + EPSF;
        float Rm = L[LNEWR+t] - e;        // read NEWR, then LP aliases (same thread)
        float P=0.f, D=0.f;
        #pragma unroll
        for (int j=0;j<3;j++){
            float a=sm[OMISC+1+j], p=sm[OMISC+4+j];
            float tt = ex2a(-p * lg2a(a*Rm));
            P += tt; D += p*tt;
        }
        L[LP+t]=P; L[LGPRE+t]=D/Rm; L[LENC+t]=enc;
    }
    __syncwarp();
    // S/F reduction: full-warp shfl tree
    {
        float Pv = (t<NN)? L[LP+t]   : 0.f;
        float Fv = (t<NN)? L[LFCR+t] : 0.f;
        #pragma unroll
        for (int m=16;m>=1;m>>=1){
            Pv += __shfl_xor_sync(0xffffffffu, Pv, m);
            Fv += __shfl_xor_sync(0xffffffffu, Fv, m);
        }
        if (t==0){ L[LSC]=Pv; L[LSC+1]=Fv; }
    }
    __syncwarp();
    if (t < NN){
        float enc=L[LENC+t];
        L[LGZ+t] = L[LSC+1]*L[LGPRE+t]*2.f*enc*(1.f-enc*enc);
        if (wr) out[(size_t)6*B + (size_t)batch*NN + t] = L[LSC]*L[LFCR+t];
    }
    __syncwarp();
    // I: ga2 from register h2 -> smem (LGT over dead feat)
    {
        const u64 SGN = 0x8000000080000000ULL;
        u64 one2 = pk2(1.0f);
        #pragma unroll
        for (int i=0;i<4;i++){
            u64 w2p=pk2(sm[OW2+s+16*i]);
            u64* gr=(u64*)(L+LGT+(s+16*i)*20) + 5*half;
            #pragma unroll
            for (int q=0;q<5;q++){
                u64 h2v=acc[i*5+q];
                u64 d = fma2o(h2v ^ SGN, h2v, one2);
                u64 gzq = *(const u64*)(L+LGZ+2*(5*half+q));
                gr[q] = mul2(mul2(gzq,w2p), d);
            }
        }
    }
    __syncwarp();
    // J: GEMM3 (gh1 = ga2 @ W1^T) with paired weight loads; ga1 overwrites LH1
    #pragma unroll
    for (int v=0; v<20; v++) acc[v]=0ull;
    {
        const u64* W1u = (const u64*)(sm + OW1);      // row stride 33 u64
        #pragma unroll 4
        for (int kk=0; kk<32; kk++){
            u64 pA=W1u[ s      *33+kk], pB=W1u[(s+16)*33+kk];
            u64 pC=W1u[(s+32)*33+kk],   pD=W1u[(s+48)*33+kk];
            float a0,a1,b0_,b1_,c0,c1,d0,d1;
            upk(pA,a0,a1); upk(pB,b0_,b1_); upk(pC,c0,c1); upk(pD,d0,d1);
            const u64* ap0=(const u64*)(L+LGT+(2*kk  )*20) + 5*half;
            const u64* ap1=(const u64*)(L+LGT+(2*kk+1)*20) + 5*half;
            u64 wA=pk2(a0), wB=pk2(b0_), wC=pk2(c0), wD=pk2(d0);
            #pragma unroll
            for (int q=0;q<5;q++){ u64 av=ap0[q];
                fma2(acc[q],wA,av); fma2(acc[5+q],wB,av);
                fma2(acc[10+q],wC,av); fma2(acc[15+q],wD,av); }
            wA=pk2(a1); wB=pk2(b1_); wC=pk2(c1); wD=pk2(d1);
            #pragma unroll
            for (int q=0;q<5;q++){ u64 av=ap1[q];
                fma2(acc[q],wA,av); fma2(acc[5+q],wB,av);
                fma2(acc[10+q],wC,av); fma2(acc[15+q],wD,av); }
        }
    }
    {
        const u64 SGN = 0x8000000080000000ULL;
        u64 one2 = pk2(1.0f);
        #pragma unroll
        for (int i=0;i<4;i++){
            u64* hr=(u64*)(L+LH1+(s+16*i)*20) + 5*half;
            #pragma unroll
            for (int q=0;q<5;q++){
                u64 h1v=hr[q];
                u64 d = fma2o(h1v ^ SGN, h1v, one2);
                hr[q] = mul2(acc[i*5+q], d);
            }
        }
    }
    __syncwarp();
    // K: GEMM4 gfeat[n][i] = sum_k ga1[k][n] W0[i][k]  (paired weights; LGF over dead LGT)
    if (s < 15){
        const u64* W0u = (const u64*)(sm + OW0);      // row stride 33 u64
        u64 a4[5];
        #pragma unroll
        for (int q=0;q<5;q++) a4[q]=0ull;
        #pragma unroll 4
        for (int kk=0; kk<32; kk++){
            u64 pw = W0u[s*33+kk];
            float w0_,w1_; upk(pw,w0_,w1_);
            const u64* ap0=(const u64*)(L+LH1+(2*kk  )*20) + 5*half;
            const u64* ap1=(const u64*)(L+LH1+(2*kk+1)*20) + 5*half;
            u64 w=pk2(w0_);
            #pragma unroll
            for (int q=0;q<5;q++) fma2(a4[q],w,ap0[q]);
            w=pk2(w1_);
            #pragma unroll
            for (int q=0;q<5;q++) fma2(a4[q],w,ap1[q]);
        }
        #pragma unroll
        for (int q=0;q<5;q++){
            float lo,hi; upk(a4[q],lo,hi);
            int n0 = 10*half + 2*q;
            L[LGF+n0*16+s]=lo; L[LGF+(n0+1)*16+s]=hi;
        }
    }
    __syncwarp();
    // L: parallel tail — force over 6 threads, gO over 18, then torque over 3
    if (t < 6){
        int c = t>>1, nh = t&1;
        float f=0.f; const float* O=L+LSO;
        #pragma unroll 2
        for (int n=nh*10; n<nh*10+10; n++){
            const float* g=L+LGF+n*16; const float* NO=L+LNOR+n*9;
            f += g[0]*O[c*3]+g[1]*O[c*3+1]+g[2]*O[c*3+2];
            f += g[3]*NO[c*3]+g[4]*NO[c*3+1]+g[5]*NO[c*3+2];
        }
        f += __shfl_xor_sync(0x3fu, f, 1);
        if (nh==0 && wr) out[(size_t)batch*3+c]=f;
    }
    if (t >= 8 && t < 26){
        int u = t-8; int c = u>>1, nh = u&1;
        int a = c/3, bb = c%3;
        float g2=0.f;
        #pragma unroll 2
        for (int n=nh*10; n<nh*10+10; n++){
            const float* g=L+LGF+n*16; const float* NO=L+LNOR+n*9;
            g2 += L[LNDN+n*3+a]*g[bb];
            g2 += g[6+3*bb+0]*NO[a*3+0]+g[6+3*bb+1]*NO[a*3+1]+g[6+3*bb+2]*NO[a*3+2];
        }
        g2 += __shfl_xor_sync(0x03FFFF00u, g2, 1);
        if (nh==0) L[LGO+a*3+bb]=g2;
    }
    __syncwarp();
    if (t < 3 && wr){
        const float* gO=L+LGO; const float* O=L+LSO;
        int i1 = (t==2)?0:(t+1), i2 = (t==0)?2:(t-1);
        float tq=0.f;
        #pragma unroll
        for (int c=0;c<3;c++)
            tq += gO[i1*3+c]*O[i2*3+c] - gO[i2*3+c]*O[i1*3+c];
        out[(size_t)3*B+(size_t)batch*3+t]=tq;
    }
}

extern "C" void kernel_launch(void* const* d_in, const int* in_sizes, int n_in,
                              void* d_out, int out_size) {
    const float* dr  = (const float*)d_in[0];
    const float* ori = (const float*)d_in[1];
    const float* nor = (const float*)d_in[2];
    const float* W0  = (const float*)d_in[3];
    const float* b0  = (const float*)d_in[4];
    const float* W1  = (const float*)d_in[5];
    const float* b1  = (const float*)d_in[6];
    const float* W2  = (const float*)d_in[7];
    const float* b2  = (const float*)d_in[8];
    const float* f1  = (const float*)d_in[9];
    const float* f2  = (const float*)d_in[10];
    float* out = (float*)d_out;

    int B = in_sizes[0] / (NBC * 3);
    int blocks = (B + LPB - 1) / LPB;
    size_t shmem = (size_t)SMEM_FLOATS * sizeof(float);
    cudaFuncSetAttribute(ep_kernel, cudaFuncAttributeMaxDynamicSharedMemorySize, (int)shmem);
    ep_kernel<<<blocks, TPB, shmem>>>(dr, ori, nor, W0, b0, W1, b1, W2, b2, f1, f2, out, B);
}